// round 5
// baseline (speedup 1.0000x reference)
#include <cuda_runtime.h>
#include <cstdint>

#define N_NODES 100000
#define N_EDGES 1250000
#define D_IN 32
#define H 64
#define SCAN_B 1024
#define NB ((N_NODES + SCAN_B - 1) / SCAN_B)   // 98
#define MLPB ((N_NODES + 31) / 32)             // 3125 blocks, 4 nodes/warp
#define HISTB 1024                              // hist blocks appended to MLP grid

// scratch
__device__ float g_h[(size_t)N_NODES * H];
__device__ int   g_deg[N_NODES];
__device__ int   g_off[N_NODES + 1];
__device__ int   g_pos[N_NODES];
__device__ int   g_csr_col[N_EDGES];
__device__ int   g_flag[NB];                    // decoupled-lookback: agg+1 (0 = not ready)

// ---- packed f32x2 helpers (sm_103a dual-FMA) --------------------------------
__device__ __forceinline__ unsigned long long pk2(float lo, float hi) {
    unsigned long long r;
    asm("mov.b64 %0, {%1, %2};" : "=l"(r) : "f"(lo), "f"(hi));
    return r;
}
__device__ __forceinline__ void upk2(unsigned long long v, float& lo, float& hi) {
    asm("mov.b64 {%0, %1}, %2;" : "=f"(lo), "=f"(hi) : "l"(v));
}
__device__ __forceinline__ void fma2(unsigned long long& d, unsigned long long a,
                                     unsigned long long b) {
    asm("fma.rn.f32x2 %0, %1, %2, %0;" : "+l"(d) : "l"(a), "l"(b));
}

union F4 { float4 f; unsigned long long u[2]; };

// ---------------------------------------------------------------------------
// K1 (fat): blocks [0, MLPB) = fused node MLP (4 nodes/warp).
//   FFMA2 mainloop packs TWO CONSECUTIVE k per 64-bit operand:
//   acc = (partial over even k, partial over odd k); final = lo + hi.
//   x pairs come free from float4 staging regs; weights pre-paired in SMEM.
// blocks [MLPB, MLPB+HISTB) = degree histogram (overlaps MLP).
// ---------------------------------------------------------------------------
__global__ __launch_bounds__(256) void mlp_hist_kernel(
    const float* __restrict__ x, const int* __restrict__ ei,
    const float* __restrict__ W1, const float* __restrict__ b1,
    const float* __restrict__ g1, const float* __restrict__ be1,
    const float* __restrict__ W2, const float* __restrict__ b2,
    const float* __restrict__ g2, const float* __restrict__ be2)
{
    const int tid = threadIdx.x;

    if (blockIdx.x >= MLPB) {
        const int base = (blockIdx.x - MLPB) * 256 + tid;
        for (int e = base; e < N_EDGES; e += HISTB * 256) {
            int row = ei[e];
            if ((unsigned)row < N_NODES) atomicAdd(&g_deg[row], 1);
        }
        return;
    }

    // paired weights: sWp[kp*64 + d] = ull( W[2kp][d], W[2kp+1][d] )
    __shared__ __align__(16) unsigned long long sW1p[(D_IN / 2) * H];   // 8 KB
    __shared__ __align__(16) unsigned long long sW2p[(H / 2) * H];      // 16 KB
    __shared__ float sb1[H], sg1[H], sbe1[H];
    __shared__ float sb2[H], sg2[H], sbe2[H];
    __shared__ __align__(16) float sx[8][4][D_IN];
    __shared__ __align__(16) float sh[8][4][H];

    {
        float* w1f = (float*)sW1p;
        float* w2f = (float*)sW2p;
        for (int i = tid; i < D_IN * H; i += 256) {
            int k = i >> 6, d = i & 63;
            w1f[((k >> 1) * 64 + d) * 2 + (k & 1)] = W1[i];
        }
        for (int i = tid; i < H * H; i += 256) {
            int k = i >> 6, d = i & 63;
            w2f[((k >> 1) * 64 + d) * 2 + (k & 1)] = W2[i];
        }
    }
    if (tid < H) {
        sb1[tid] = b1[tid]; sg1[tid] = g1[tid]; sbe1[tid] = be1[tid];
        sb2[tid] = b2[tid]; sg2[tid] = g2[tid]; sbe2[tid] = be2[tid];
    }
    __syncthreads();

    const int warp = tid >> 5;
    const int lane = tid & 31;
    const int n0 = (blockIdx.x * 8 + warp) * 4;
    if (n0 >= N_NODES) return;

    #pragma unroll
    for (int j = 0; j < 4; j++)
        sx[warp][j][lane] = x[(size_t)(n0 + j) * D_IN + lane];
    __syncwarp();

    // ---- layer 1 ----
    unsigned long long a0[4], a1[4];
    #pragma unroll
    for (int j = 0; j < 4; j++) {
        a0[j] = pk2(sb1[lane],      0.0f);
        a1[j] = pk2(sb1[lane + 32], 0.0f);
    }
    #pragma unroll
    for (int k4 = 0; k4 < D_IN / 4; k4++) {
        F4 xv[4];
        #pragma unroll
        for (int j = 0; j < 4; j++) xv[j].f = *(const float4*)&sx[warp][j][k4 * 4];
        #pragma unroll
        for (int p = 0; p < 2; p++) {
            const int kp = k4 * 2 + p;
            const unsigned long long w0 = sW1p[kp * 64 + lane];
            const unsigned long long w1 = sW1p[kp * 64 + lane + 32];
            #pragma unroll
            for (int j = 0; j < 4; j++) {
                fma2(a0[j], xv[j].u[p], w0);
                fma2(a1[j], xv[j].u[p], w1);
            }
        }
    }
    {
        float s[4], q[4], v0[4], v1[4];
        #pragma unroll
        for (int j = 0; j < 4; j++) {
            float l0, h0, l1, h1;
            upk2(a0[j], l0, h0); upk2(a1[j], l1, h1);
            v0[j] = l0 + h0; v1[j] = l1 + h1;
            s[j] = v0[j] + v1[j];
            q[j] = v0[j] * v0[j] + v1[j] * v1[j];
        }
        #pragma unroll
        for (int off = 16; off > 0; off >>= 1) {
            #pragma unroll
            for (int j = 0; j < 4; j++) {
                s[j] += __shfl_xor_sync(0xffffffffu, s[j], off);
                q[j] += __shfl_xor_sync(0xffffffffu, q[j], off);
            }
        }
        #pragma unroll
        for (int j = 0; j < 4; j++) {
            const float mu  = s[j] * (1.0f / H);
            const float var = q[j] * (1.0f / H) - mu * mu;
            const float inv = rsqrtf(var + 1e-5f);
            float r0 = (v0[j] - mu) * inv * sg1[lane]      + sbe1[lane];
            float r1 = (v1[j] - mu) * inv * sg1[lane + 32] + sbe1[lane + 32];
            sh[warp][j][lane]      = fmaxf(r0, 0.0f);
            sh[warp][j][lane + 32] = fmaxf(r1, 0.0f);
        }
    }
    __syncwarp();

    // ---- layer 2 ----
    unsigned long long c0[4], c1[4];
    #pragma unroll
    for (int j = 0; j < 4; j++) {
        c0[j] = pk2(sb2[lane],      0.0f);
        c1[j] = pk2(sb2[lane + 32], 0.0f);
    }
    #pragma unroll
    for (int k4 = 0; k4 < H / 4; k4++) {
        F4 hv[4];
        #pragma unroll
        for (int j = 0; j < 4; j++) hv[j].f = *(const float4*)&sh[warp][j][k4 * 4];
        #pragma unroll
        for (int p = 0; p < 2; p++) {
            const int kp = k4 * 2 + p;
            const unsigned long long w0 = sW2p[kp * 64 + lane];
            const unsigned long long w1 = sW2p[kp * 64 + lane + 32];
            #pragma unroll
            for (int j = 0; j < 4; j++) {
                fma2(c0[j], hv[j].u[p], w0);
                fma2(c1[j], hv[j].u[p], w1);
            }
        }
    }
    {
        float s[4], q[4], v0[4], v1[4];
        #pragma unroll
        for (int j = 0; j < 4; j++) {
            float l0, h0, l1, h1;
            upk2(c0[j], l0, h0); upk2(c1[j], l1, h1);
            v0[j] = l0 + h0; v1[j] = l1 + h1;
            s[j] = v0[j] + v1[j];
            q[j] = v0[j] * v0[j] + v1[j] * v1[j];
        }
        #pragma unroll
        for (int off = 16; off > 0; off >>= 1) {
            #pragma unroll
            for (int j = 0; j < 4; j++) {
                s[j] += __shfl_xor_sync(0xffffffffu, s[j], off);
                q[j] += __shfl_xor_sync(0xffffffffu, q[j], off);
            }
        }
        #pragma unroll
        for (int j = 0; j < 4; j++) {
            const float mu  = s[j] * (1.0f / H);
            const float var = q[j] * (1.0f / H) - mu * mu;
            const float inv = rsqrtf(var + 1e-5f);
            float r0 = (v0[j] - mu) * inv * sg2[lane]      + sbe2[lane];
            float r1 = (v1[j] - mu) * inv * sg2[lane + 32] + sbe2[lane + 32];
            const size_t base = (size_t)(n0 + j) * H;
            g_h[base + lane]      = fmaxf(r0, 0.0f);
            g_h[base + lane + 32] = fmaxf(r1, 0.0f);
        }
    }
}

// ---------------------------------------------------------------------------
// K2: single-kernel exclusive scan (decoupled lookback; all 98 blocks wave-1)
// ---------------------------------------------------------------------------
__global__ __launch_bounds__(SCAN_B) void scan_kernel()
{
    __shared__ int wsum[32];
    __shared__ int sprefix;
    const int t   = threadIdx.x;
    const int bid = blockIdx.x;
    const int i   = bid * SCAN_B + t;

    int v = (i < N_NODES) ? g_deg[i] : 0;
    const int orig = v;
    #pragma unroll
    for (int o = 1; o < 32; o <<= 1) {
        int n = __shfl_up_sync(0xffffffffu, v, o);
        if ((t & 31) >= o) v += n;
    }
    if ((t & 31) == 31) wsum[t >> 5] = v;
    __syncthreads();
    if (t < 32) {
        int w = wsum[t];
        #pragma unroll
        for (int o = 1; o < 32; o <<= 1) {
            int n = __shfl_up_sync(0xffffffffu, w, o);
            if (t >= o) w += n;
        }
        wsum[t] = w;
    }
    __syncthreads();
    const int base = (t >= 32) ? wsum[(t >> 5) - 1] : 0;
    const int incl = v + base;

    if (t == SCAN_B - 1) ((volatile int*)g_flag)[bid] = incl + 1;

    if (t < 32) {
        int sum = 0;
        for (int j0 = bid - 1; j0 >= 0; j0 -= 32) {
            const int j = j0 - t;
            int av = 0;
            if (j >= 0) {
                while ((av = ((volatile int*)g_flag)[j]) == 0) {}
                av -= 1;
            }
            #pragma unroll
            for (int o = 16; o > 0; o >>= 1)
                av += __shfl_xor_sync(0xffffffffu, av, o);
            sum += av;
        }
        if (t == 0) sprefix = sum;
    }
    __syncthreads();

    if (i < N_NODES) {
        const int o = sprefix + incl - orig;
        g_off[i] = o;
        g_pos[i] = o;
    }
    if (i == 0) g_off[N_NODES] = N_EDGES;
}

// ---------------------------------------------------------------------------
// K3: scatter column ids into CSR slots
// ---------------------------------------------------------------------------
__global__ __launch_bounds__(256) void scatter_kernel(const int* __restrict__ ei)
{
    int e = blockIdx.x * 256 + threadIdx.x;
    if (e >= N_EDGES) return;
    int row = ei[e];
    int col = ei[N_EDGES + e];
    if ((unsigned)row >= N_NODES) return;
    int p = atomicAdd(&g_pos[row], 1);
    g_csr_col[p] = col;
}

// ---------------------------------------------------------------------------
// K4: pull-gather, warp per node, 4 edges in flight per warp
// (2 independent accumulators per half-warp; float4/lane = half row each).
// ---------------------------------------------------------------------------
__global__ __launch_bounds__(256) void gather_kernel(float* __restrict__ out)
{
    const int n = blockIdx.x * 8 + (threadIdx.x >> 5);
    if (n >= N_NODES) return;
    const int lane = threadIdx.x & 31;
    const int half = lane >> 4;
    const int hl   = lane & 15;

    float4 acc0 = make_float4(0.f, 0.f, 0.f, 0.f);
    float4 acc1 = make_float4(0.f, 0.f, 0.f, 0.f);

    const int start = g_off[n];
    const int end   = g_off[n + 1];

    for (int jb = start; jb < end; jb += 32) {
        const int cnt = min(32, end - jb);
        int cidx = (lane < cnt) ? g_csr_col[jb + lane] : 0;
        for (int it = 0; it < cnt; it += 4) {
            const int t0 = it + 2 * half;
            const int t1 = t0 + 1;
            const int c0 = __shfl_sync(0xffffffffu, cidx, t0 & 31);
            const int c1 = __shfl_sync(0xffffffffu, cidx, t1 & 31);
            if (t0 < cnt) {
                const float4 v = __ldg((const float4*)(g_h + (size_t)c0 * H) + hl);
                acc0.x += v.x; acc0.y += v.y; acc0.z += v.z; acc0.w += v.w;
            }
            if (t1 < cnt) {
                const float4 v = __ldg((const float4*)(g_h + (size_t)c1 * H) + hl);
                acc1.x += v.x; acc1.y += v.y; acc1.z += v.z; acc1.w += v.w;
            }
        }
    }

    acc0.x += acc1.x; acc0.y += acc1.y; acc0.z += acc1.z; acc0.w += acc1.w;
    acc0.x += __shfl_down_sync(0xffffffffu, acc0.x, 16);
    acc0.y += __shfl_down_sync(0xffffffffu, acc0.y, 16);
    acc0.z += __shfl_down_sync(0xffffffffu, acc0.z, 16);
    acc0.w += __shfl_down_sync(0xffffffffu, acc0.w, 16);

    if (lane < 16) {
        const float4 self = __ldg((const float4*)(g_h + (size_t)n * H) + hl);
        acc0.x += self.x; acc0.y += self.y; acc0.z += self.z; acc0.w += self.w;
        ((float4*)out)[(size_t)n * 16 + hl] = acc0;
    }
}

// ---------------------------------------------------------------------------
// inputs: x, edge_index(int32 [2,E]), W1, b1, g1, beta1, W2, b2, g2, beta2
// ---------------------------------------------------------------------------
extern "C" void kernel_launch(void* const* d_in, const int* in_sizes, int n_in,
                              void* d_out, int out_size)
{
    const float* x   = (const float*)d_in[0];
    const int*   ei  = (const int*)d_in[1];
    const float* W1  = (const float*)d_in[2];
    const float* b1  = (const float*)d_in[3];
    const float* g1  = (const float*)d_in[4];
    const float* be1 = (const float*)d_in[5];
    const float* W2  = (const float*)d_in[6];
    const float* b2  = (const float*)d_in[7];
    const float* g2  = (const float*)d_in[8];
    const float* be2 = (const float*)d_in[9];
    float* out = (float*)d_out;

    void* p_deg  = nullptr;
    void* p_flag = nullptr;
    cudaGetSymbolAddress(&p_deg,  g_deg);
    cudaGetSymbolAddress(&p_flag, g_flag);
    cudaMemsetAsync(p_deg,  0, sizeof(int) * N_NODES);
    cudaMemsetAsync(p_flag, 0, sizeof(int) * NB);

    mlp_hist_kernel<<<MLPB + HISTB, 256>>>(x, ei, W1, b1, g1, be1, W2, b2, g2, be2);
    scan_kernel<<<NB, SCAN_B>>>();
    scatter_kernel<<<(N_EDGES + 255) / 256, 256>>>(ei);
    gather_kernel<<<(N_NODES + 7) / 8, 256>>>(out);
}

// round 6
// speedup vs baseline: 1.3394x; 1.3394x over previous
#include <cuda_runtime.h>
#include <cstdint>

#define N_NODES 100000
#define N_EDGES 1250000
#define D_IN 32
#define H 64
#define SCAN_B 1024
#define NB ((N_NODES + SCAN_B - 1) / SCAN_B)   // 98
#define MLPB ((N_NODES + 31) / 32)             // 3125 blocks, 4 nodes/warp
#define HISTB 512                               // hist blocks prepended to MLP grid

// scratch
__device__ float g_h[(size_t)N_NODES * H];
__device__ int   g_deg[N_NODES];
__device__ int   g_off[N_NODES + 1];
__device__ int   g_pos[N_NODES];
__device__ int   g_csr_col[N_EDGES];
__device__ int   g_flag[NB];                    // decoupled-lookback: agg+1 (0 = not ready)

// ---- packed f32x2 helpers (sm_103a dual-FMA) --------------------------------
__device__ __forceinline__ unsigned long long pk2(float lo, float hi) {
    unsigned long long r;
    asm("mov.b64 %0, {%1, %2};" : "=l"(r) : "f"(lo), "f"(hi));
    return r;
}
__device__ __forceinline__ void upk2(unsigned long long v, float& lo, float& hi) {
    asm("mov.b64 {%0, %1}, %2;" : "=f"(lo), "=f"(hi) : "l"(v));
}
__device__ __forceinline__ void fma2(unsigned long long& d, unsigned long long a,
                                     unsigned long long b) {
    asm("fma.rn.f32x2 %0, %1, %2, %0;" : "+l"(d) : "l"(a), "l"(b));
}

// ---------------------------------------------------------------------------
// K1 (fat): blocks [0, HISTB) = degree histogram (runs in wave 1, overlaps MLP)
//           blocks [HISTB, HISTB+MLPB) = fused node MLP (4 nodes/warp, FFMA2)
// ---------------------------------------------------------------------------
__global__ __launch_bounds__(256) void mlp_hist_kernel(
    const float* __restrict__ x, const int* __restrict__ ei,
    const float* __restrict__ W1, const float* __restrict__ b1,
    const float* __restrict__ g1, const float* __restrict__ be1,
    const float* __restrict__ W2, const float* __restrict__ b2,
    const float* __restrict__ g2, const float* __restrict__ be2)
{
    const int tid = threadIdx.x;

    if (blockIdx.x < HISTB) {
        // ---- histogram part (memory/atomic bound; overlaps FMA-bound MLP) ----
        const int base = blockIdx.x * 256 + tid;
        for (int e = base; e < N_EDGES; e += HISTB * 256) {
            int row = ei[e];
            if ((unsigned)row < N_NODES) atomicAdd(&g_deg[row], 1);
        }
        return;
    }

    // ---- MLP part ----
    __shared__ __align__(16) float sW1p[D_IN * H];   // paired: [k*32+c]=(W[k][c],W[k][c+32])
    __shared__ __align__(16) float sW2p[H * H];
    __shared__ float sb1[H], sg1[H], sbe1[H];
    __shared__ float sb2[H], sg2[H], sbe2[H];
    __shared__ __align__(16) float sx[8][4][D_IN];
    __shared__ __align__(16) float sh[8][4][H];

    for (int i = tid; i < D_IN * H; i += 256) {
        int k = i >> 6, d = i & 63;
        sW1p[(k * 32 + (d & 31)) * 2 + (d >> 5)] = W1[i];
    }
    for (int i = tid; i < H * H; i += 256) {
        int k = i >> 6, d = i & 63;
        sW2p[(k * 32 + (d & 31)) * 2 + (d >> 5)] = W2[i];
    }
    if (tid < H) {
        sb1[tid] = b1[tid]; sg1[tid] = g1[tid]; sbe1[tid] = be1[tid];
        sb2[tid] = b2[tid]; sg2[tid] = g2[tid]; sbe2[tid] = be2[tid];
    }
    __syncthreads();

    const int warp = tid >> 5;
    const int lane = tid & 31;
    const int n0 = ((blockIdx.x - HISTB) * 8 + warp) * 4;
    if (n0 >= N_NODES) return;

    const unsigned long long* W1p64 = (const unsigned long long*)sW1p;
    const unsigned long long* W2p64 = (const unsigned long long*)sW2p;

    #pragma unroll
    for (int j = 0; j < 4; j++)
        sx[warp][j][lane] = x[(size_t)(n0 + j) * D_IN + lane];
    __syncwarp();

    // ---- layer 1 ----
    unsigned long long a[4];
    {
        const unsigned long long bias = pk2(sb1[lane], sb1[lane + 32]);
        #pragma unroll
        for (int j = 0; j < 4; j++) a[j] = bias;
    }
    #pragma unroll
    for (int k4 = 0; k4 < D_IN / 4; k4++) {
        float4 xv[4];
        #pragma unroll
        for (int j = 0; j < 4; j++) xv[j] = *(const float4*)&sx[warp][j][k4 * 4];
        #pragma unroll
        for (int kk = 0; kk < 4; kk++) {
            const int k = k4 * 4 + kk;
            const unsigned long long w = W1p64[k * 32 + lane];
            #pragma unroll
            for (int j = 0; j < 4; j++) {
                const float xx = ((const float*)&xv[j])[kk];
                fma2(a[j], pk2(xx, xx), w);
            }
        }
    }
    {
        float s[4], q[4], v0[4], v1[4];
        #pragma unroll
        for (int j = 0; j < 4; j++) {
            upk2(a[j], v0[j], v1[j]);
            s[j] = v0[j] + v1[j];
            q[j] = v0[j] * v0[j] + v1[j] * v1[j];
        }
        #pragma unroll
        for (int off = 16; off > 0; off >>= 1) {
            #pragma unroll
            for (int j = 0; j < 4; j++) {
                s[j] += __shfl_xor_sync(0xffffffffu, s[j], off);
                q[j] += __shfl_xor_sync(0xffffffffu, q[j], off);
            }
        }
        #pragma unroll
        for (int j = 0; j < 4; j++) {
            const float mu  = s[j] * (1.0f / H);
            const float var = q[j] * (1.0f / H) - mu * mu;
            const float inv = rsqrtf(var + 1e-5f);
            float r0 = (v0[j] - mu) * inv * sg1[lane]      + sbe1[lane];
            float r1 = (v1[j] - mu) * inv * sg1[lane + 32] + sbe1[lane + 32];
            sh[warp][j][lane]      = fmaxf(r0, 0.0f);
            sh[warp][j][lane + 32] = fmaxf(r1, 0.0f);
        }
    }
    __syncwarp();

    // ---- layer 2 ----
    unsigned long long c[4];
    {
        const unsigned long long bias = pk2(sb2[lane], sb2[lane + 32]);
        #pragma unroll
        for (int j = 0; j < 4; j++) c[j] = bias;
    }
    #pragma unroll
    for (int k4 = 0; k4 < H / 4; k4++) {
        float4 hv[4];
        #pragma unroll
        for (int j = 0; j < 4; j++) hv[j] = *(const float4*)&sh[warp][j][k4 * 4];
        #pragma unroll
        for (int kk = 0; kk < 4; kk++) {
            const int k = k4 * 4 + kk;
            const unsigned long long w = W2p64[k * 32 + lane];
            #pragma unroll
            for (int j = 0; j < 4; j++) {
                const float hh = ((const float*)&hv[j])[kk];
                fma2(c[j], pk2(hh, hh), w);
            }
        }
    }
    {
        float s[4], q[4], v0[4], v1[4];
        #pragma unroll
        for (int j = 0; j < 4; j++) {
            upk2(c[j], v0[j], v1[j]);
            s[j] = v0[j] + v1[j];
            q[j] = v0[j] * v0[j] + v1[j] * v1[j];
        }
        #pragma unroll
        for (int off = 16; off > 0; off >>= 1) {
            #pragma unroll
            for (int j = 0; j < 4; j++) {
                s[j] += __shfl_xor_sync(0xffffffffu, s[j], off);
                q[j] += __shfl_xor_sync(0xffffffffu, q[j], off);
            }
        }
        #pragma unroll
        for (int j = 0; j < 4; j++) {
            const float mu  = s[j] * (1.0f / H);
            const float var = q[j] * (1.0f / H) - mu * mu;
            const float inv = rsqrtf(var + 1e-5f);
            float r0 = (v0[j] - mu) * inv * sg2[lane]      + sbe2[lane];
            float r1 = (v1[j] - mu) * inv * sg2[lane + 32] + sbe2[lane + 32];
            const size_t base = (size_t)(n0 + j) * H;
            g_h[base + lane]      = fmaxf(r0, 0.0f);
            g_h[base + lane + 32] = fmaxf(r1, 0.0f);
        }
    }
}

// ---------------------------------------------------------------------------
// K2: single-kernel exclusive scan (decoupled lookback; all 98 blocks wave-1)
// ---------------------------------------------------------------------------
__global__ __launch_bounds__(SCAN_B) void scan_kernel()
{
    __shared__ int wsum[32];
    __shared__ int sprefix;
    const int t   = threadIdx.x;
    const int bid = blockIdx.x;
    const int i   = bid * SCAN_B + t;

    int v = (i < N_NODES) ? g_deg[i] : 0;
    const int orig = v;
    #pragma unroll
    for (int o = 1; o < 32; o <<= 1) {
        int n = __shfl_up_sync(0xffffffffu, v, o);
        if ((t & 31) >= o) v += n;
    }
    if ((t & 31) == 31) wsum[t >> 5] = v;
    __syncthreads();
    if (t < 32) {
        int w = wsum[t];
        #pragma unroll
        for (int o = 1; o < 32; o <<= 1) {
            int n = __shfl_up_sync(0xffffffffu, w, o);
            if (t >= o) w += n;
        }
        wsum[t] = w;
    }
    __syncthreads();
    const int base = (t >= 32) ? wsum[(t >> 5) - 1] : 0;
    const int incl = v + base;

    if (t == SCAN_B - 1) ((volatile int*)g_flag)[bid] = incl + 1;

    if (t < 32) {
        int sum = 0;
        for (int j0 = bid - 1; j0 >= 0; j0 -= 32) {
            const int j = j0 - t;
            int av = 0;
            if (j >= 0) {
                while ((av = ((volatile int*)g_flag)[j]) == 0) {}
                av -= 1;
            }
            #pragma unroll
            for (int o = 16; o > 0; o >>= 1)
                av += __shfl_xor_sync(0xffffffffu, av, o);
            sum += av;
        }
        if (t == 0) sprefix = sum;
    }
    __syncthreads();

    if (i < N_NODES) {
        const int o = sprefix + incl - orig;
        g_off[i] = o;
        g_pos[i] = o;
    }
    if (i == 0) g_off[N_NODES] = N_EDGES;
}

// ---------------------------------------------------------------------------
// K3: scatter column ids into CSR slots. 4 edges per thread (int4 index loads).
// ---------------------------------------------------------------------------
__global__ __launch_bounds__(256) void scatter_kernel(const int* __restrict__ ei)
{
    const int e4 = (blockIdx.x * 256 + threadIdx.x) * 4;
    if (e4 >= N_EDGES) return;
    const int4 rows = *(const int4*)&ei[e4];
    const int4 cols = *(const int4*)&ei[N_EDGES + e4];
    #pragma unroll
    for (int j = 0; j < 4; j++) {
        const int row = (&rows.x)[j];
        const int col = (&cols.x)[j];
        if ((unsigned)row < N_NODES) {
            int p = atomicAdd(&g_pos[row], 1);
            g_csr_col[p] = col;
        }
    }
}

// ---------------------------------------------------------------------------
// K4: pull-gather, warp per node, 2 edges in flight per warp (R4 structure).
// Self row issued before the edge loop to overlap its latency.
// ---------------------------------------------------------------------------
__global__ __launch_bounds__(256) void gather_kernel(float* __restrict__ out)
{
    const int n = blockIdx.x * 8 + (threadIdx.x >> 5);
    if (n >= N_NODES) return;
    const int lane = threadIdx.x & 31;
    const int half = lane >> 4;
    const int hl   = lane & 15;

    const float4 self = __ldg((const float4*)(g_h + (size_t)n * H) + hl);  // early issue

    float4 acc = make_float4(0.f, 0.f, 0.f, 0.f);

    const int start = g_off[n];
    const int end   = g_off[n + 1];

    for (int jb = start; jb < end; jb += 32) {
        const int cnt = min(32, end - jb);
        int cidx = (lane < cnt) ? g_csr_col[jb + lane] : 0;
        const int iters = (cnt + 1) >> 1;
        for (int it = 0; it < iters; it++) {
            const int tt = 2 * it + half;
            const int cc = __shfl_sync(0xffffffffu, cidx, tt & 31);
            if (tt < cnt) {
                const float4 v = __ldg((const float4*)(g_h + (size_t)cc * H) + hl);
                acc.x += v.x; acc.y += v.y; acc.z += v.z; acc.w += v.w;
            }
        }
    }

    acc.x += __shfl_down_sync(0xffffffffu, acc.x, 16);
    acc.y += __shfl_down_sync(0xffffffffu, acc.y, 16);
    acc.z += __shfl_down_sync(0xffffffffu, acc.z, 16);
    acc.w += __shfl_down_sync(0xffffffffu, acc.w, 16);

    if (lane < 16) {
        acc.x += self.x; acc.y += self.y; acc.z += self.z; acc.w += self.w;
        ((float4*)out)[(size_t)n * 16 + hl] = acc;
    }
}

// ---------------------------------------------------------------------------
// inputs: x, edge_index(int32 [2,E]), W1, b1, g1, beta1, W2, b2, g2, beta2
// ---------------------------------------------------------------------------
extern "C" void kernel_launch(void* const* d_in, const int* in_sizes, int n_in,
                              void* d_out, int out_size)
{
    const float* x   = (const float*)d_in[0];
    const int*   ei  = (const int*)d_in[1];
    const float* W1  = (const float*)d_in[2];
    const float* b1  = (const float*)d_in[3];
    const float* g1  = (const float*)d_in[4];
    const float* be1 = (const float*)d_in[5];
    const float* W2  = (const float*)d_in[6];
    const float* b2  = (const float*)d_in[7];
    const float* g2  = (const float*)d_in[8];
    const float* be2 = (const float*)d_in[9];
    float* out = (float*)d_out;

    void* p_deg  = nullptr;
    void* p_flag = nullptr;
    cudaGetSymbolAddress(&p_deg,  g_deg);
    cudaGetSymbolAddress(&p_flag, g_flag);
    cudaMemsetAsync(p_deg,  0, sizeof(int) * N_NODES);
    cudaMemsetAsync(p_flag, 0, sizeof(int) * NB);

    mlp_hist_kernel<<<HISTB + MLPB, 256>>>(x, ei, W1, b1, g1, be1, W2, b2, g2, be2);
    scan_kernel<<<NB, SCAN_B>>>();
    scatter_kernel<<<(N_EDGES / 4 + 255) / 256, 256>>>(ei);
    gather_kernel<<<(N_NODES + 7) / 8, 256>>>(out);
}

// round 7
// speedup vs baseline: 1.3800x; 1.0303x over previous
#include <cuda_runtime.h>
#include <cstdint>

#define N_NODES 100000
#define N_EDGES 1250000
#define D_IN 32
#define H 64
#define SCAN_B 1024
#define NB ((N_NODES + SCAN_B - 1) / SCAN_B)   // 98
#define MLPB ((N_NODES + 31) / 32)             // 3125 blocks, 4 nodes/warp

// scratch
__device__ float g_h[(size_t)N_NODES * H];
__device__ int   g_deg[N_NODES];
__device__ int   g_off[N_NODES + 1];
__device__ int   g_pos[N_NODES];
__device__ int   g_csr_col[N_EDGES];
__device__ int   g_flag[NB];                    // decoupled-lookback: agg+1 (0 = not ready)

// ---- packed f32x2 helpers (sm_103a dual-FMA) --------------------------------
__device__ __forceinline__ unsigned long long pk2(float lo, float hi) {
    unsigned long long r;
    asm("mov.b64 %0, {%1, %2};" : "=l"(r) : "f"(lo), "f"(hi));
    return r;
}
__device__ __forceinline__ void upk2(unsigned long long v, float& lo, float& hi) {
    asm("mov.b64 {%0, %1}, %2;" : "=f"(lo), "=f"(hi) : "l"(v));
}
__device__ __forceinline__ void fma2(unsigned long long& d, unsigned long long a,
                                     unsigned long long b) {
    asm("fma.rn.f32x2 %0, %1, %2, %0;" : "+l"(d) : "l"(a), "l"(b));
}

// ---------------------------------------------------------------------------
// K1: fused node MLP (4 nodes/warp, FFMA2 mainloop) -> g_h
// ---------------------------------------------------------------------------
__global__ __launch_bounds__(256) void mlp_kernel(
    const float* __restrict__ x,
    const float* __restrict__ W1, const float* __restrict__ b1,
    const float* __restrict__ g1, const float* __restrict__ be1,
    const float* __restrict__ W2, const float* __restrict__ b2,
    const float* __restrict__ g2, const float* __restrict__ be2)
{
    const int tid = threadIdx.x;

    __shared__ __align__(16) float sW1p[D_IN * H];   // paired: [k*32+c]=(W[k][c],W[k][c+32])
    __shared__ __align__(16) float sW2p[H * H];
    __shared__ float sb1[H], sg1[H], sbe1[H];
    __shared__ float sb2[H], sg2[H], sbe2[H];
    __shared__ __align__(16) float sx[8][4][D_IN];
    __shared__ __align__(16) float sh[8][4][H];

    for (int i = tid; i < D_IN * H; i += 256) {
        int k = i >> 6, d = i & 63;
        sW1p[(k * 32 + (d & 31)) * 2 + (d >> 5)] = W1[i];
    }
    for (int i = tid; i < H * H; i += 256) {
        int k = i >> 6, d = i & 63;
        sW2p[(k * 32 + (d & 31)) * 2 + (d >> 5)] = W2[i];
    }
    if (tid < H) {
        sb1[tid] = b1[tid]; sg1[tid] = g1[tid]; sbe1[tid] = be1[tid];
        sb2[tid] = b2[tid]; sg2[tid] = g2[tid]; sbe2[tid] = be2[tid];
    }
    __syncthreads();

    const int warp = tid >> 5;
    const int lane = tid & 31;
    const int n0 = (blockIdx.x * 8 + warp) * 4;
    if (n0 >= N_NODES) return;

    const unsigned long long* W1p64 = (const unsigned long long*)sW1p;
    const unsigned long long* W2p64 = (const unsigned long long*)sW2p;

    #pragma unroll
    for (int j = 0; j < 4; j++)
        sx[warp][j][lane] = x[(size_t)(n0 + j) * D_IN + lane];
    __syncwarp();

    // ---- layer 1 ----
    unsigned long long a[4];
    {
        const unsigned long long bias = pk2(sb1[lane], sb1[lane + 32]);
        #pragma unroll
        for (int j = 0; j < 4; j++) a[j] = bias;
    }
    #pragma unroll
    for (int k4 = 0; k4 < D_IN / 4; k4++) {
        float4 xv[4];
        #pragma unroll
        for (int j = 0; j < 4; j++) xv[j] = *(const float4*)&sx[warp][j][k4 * 4];
        #pragma unroll
        for (int kk = 0; kk < 4; kk++) {
            const int k = k4 * 4 + kk;
            const unsigned long long w = W1p64[k * 32 + lane];
            #pragma unroll
            for (int j = 0; j < 4; j++) {
                const float xx = ((const float*)&xv[j])[kk];
                fma2(a[j], pk2(xx, xx), w);
            }
        }
    }
    {
        float s[4], q[4], v0[4], v1[4];
        #pragma unroll
        for (int j = 0; j < 4; j++) {
            upk2(a[j], v0[j], v1[j]);
            s[j] = v0[j] + v1[j];
            q[j] = v0[j] * v0[j] + v1[j] * v1[j];
        }
        #pragma unroll
        for (int off = 16; off > 0; off >>= 1) {
            #pragma unroll
            for (int j = 0; j < 4; j++) {
                s[j] += __shfl_xor_sync(0xffffffffu, s[j], off);
                q[j] += __shfl_xor_sync(0xffffffffu, q[j], off);
            }
        }
        #pragma unroll
        for (int j = 0; j < 4; j++) {
            const float mu  = s[j] * (1.0f / H);
            const float var = q[j] * (1.0f / H) - mu * mu;
            const float inv = rsqrtf(var + 1e-5f);
            float r0 = (v0[j] - mu) * inv * sg1[lane]      + sbe1[lane];
            float r1 = (v1[j] - mu) * inv * sg1[lane + 32] + sbe1[lane + 32];
            sh[warp][j][lane]      = fmaxf(r0, 0.0f);
            sh[warp][j][lane + 32] = fmaxf(r1, 0.0f);
        }
    }
    __syncwarp();

    // ---- layer 2 ----
    unsigned long long c[4];
    {
        const unsigned long long bias = pk2(sb2[lane], sb2[lane + 32]);
        #pragma unroll
        for (int j = 0; j < 4; j++) c[j] = bias;
    }
    #pragma unroll
    for (int k4 = 0; k4 < H / 4; k4++) {
        float4 hv[4];
        #pragma unroll
        for (int j = 0; j < 4; j++) hv[j] = *(const float4*)&sh[warp][j][k4 * 4];
        #pragma unroll
        for (int kk = 0; kk < 4; kk++) {
            const int k = k4 * 4 + kk;
            const unsigned long long w = W2p64[k * 32 + lane];
            #pragma unroll
            for (int j = 0; j < 4; j++) {
                const float hh = ((const float*)&hv[j])[kk];
                fma2(c[j], pk2(hh, hh), w);
            }
        }
    }
    {
        float s[4], q[4], v0[4], v1[4];
        #pragma unroll
        for (int j = 0; j < 4; j++) {
            upk2(c[j], v0[j], v1[j]);
            s[j] = v0[j] + v1[j];
            q[j] = v0[j] * v0[j] + v1[j] * v1[j];
        }
        #pragma unroll
        for (int off = 16; off > 0; off >>= 1) {
            #pragma unroll
            for (int j = 0; j < 4; j++) {
                s[j] += __shfl_xor_sync(0xffffffffu, s[j], off);
                q[j] += __shfl_xor_sync(0xffffffffu, q[j], off);
            }
        }
        #pragma unroll
        for (int j = 0; j < 4; j++) {
            const float mu  = s[j] * (1.0f / H);
            const float var = q[j] * (1.0f / H) - mu * mu;
            const float inv = rsqrtf(var + 1e-5f);
            float r0 = (v0[j] - mu) * inv * sg2[lane]      + sbe2[lane];
            float r1 = (v1[j] - mu) * inv * sg2[lane + 32] + sbe2[lane + 32];
            const size_t base = (size_t)(n0 + j) * H;
            g_h[base + lane]      = fmaxf(r0, 0.0f);
            g_h[base + lane + 32] = fmaxf(r1, 0.0f);
        }
    }
}

// ---------------------------------------------------------------------------
// K2b: degree histogram (4 edges/thread, int4 loads, fire-and-forget atomics)
// ---------------------------------------------------------------------------
__global__ __launch_bounds__(256) void hist_kernel(const int* __restrict__ ei)
{
    const int e4 = (blockIdx.x * 256 + threadIdx.x) * 4;
    if (e4 >= N_EDGES) return;
    const int4 rows = *(const int4*)&ei[e4];
    #pragma unroll
    for (int j = 0; j < 4; j++) {
        const int row = (&rows.x)[j];
        if ((unsigned)row < N_NODES) atomicAdd(&g_deg[row], 1);
    }
}

// ---------------------------------------------------------------------------
// K3b: single-kernel exclusive scan (decoupled lookback; 98 blocks all wave-1)
// ---------------------------------------------------------------------------
__global__ __launch_bounds__(SCAN_B) void scan_kernel()
{
    __shared__ int wsum[32];
    __shared__ int sprefix;
    const int t   = threadIdx.x;
    const int bid = blockIdx.x;
    const int i   = bid * SCAN_B + t;

    int v = (i < N_NODES) ? g_deg[i] : 0;
    const int orig = v;
    #pragma unroll
    for (int o = 1; o < 32; o <<= 1) {
        int n = __shfl_up_sync(0xffffffffu, v, o);
        if ((t & 31) >= o) v += n;
    }
    if ((t & 31) == 31) wsum[t >> 5] = v;
    __syncthreads();
    if (t < 32) {
        int w = wsum[t];
        #pragma unroll
        for (int o = 1; o < 32; o <<= 1) {
            int n = __shfl_up_sync(0xffffffffu, w, o);
            if (t >= o) w += n;
        }
        wsum[t] = w;
    }
    __syncthreads();
    const int base = (t >= 32) ? wsum[(t >> 5) - 1] : 0;
    const int incl = v + base;

    if (t == SCAN_B - 1) ((volatile int*)g_flag)[bid] = incl + 1;

    if (t < 32) {
        int sum = 0;
        for (int j0 = bid - 1; j0 >= 0; j0 -= 32) {
            const int j = j0 - t;
            int av = 0;
            if (j >= 0) {
                while ((av = ((volatile int*)g_flag)[j]) == 0) {}
                av -= 1;
            }
            #pragma unroll
            for (int o = 16; o > 0; o >>= 1)
                av += __shfl_xor_sync(0xffffffffu, av, o);
            sum += av;
        }
        if (t == 0) sprefix = sum;
    }
    __syncthreads();

    if (i < N_NODES) {
        const int o = sprefix + incl - orig;
        g_off[i] = o;
        g_pos[i] = o;
    }
    if (i == 0) g_off[N_NODES] = N_EDGES;
}

// ---------------------------------------------------------------------------
// K4b: scatter column ids into CSR slots (4 edges/thread, int4 index loads)
// ---------------------------------------------------------------------------
__global__ __launch_bounds__(256) void scatter_kernel(const int* __restrict__ ei)
{
    const int e4 = (blockIdx.x * 256 + threadIdx.x) * 4;
    if (e4 >= N_EDGES) return;
    const int4 rows = *(const int4*)&ei[e4];
    const int4 cols = *(const int4*)&ei[N_EDGES + e4];
    #pragma unroll
    for (int j = 0; j < 4; j++) {
        const int row = (&rows.x)[j];
        const int col = (&cols.x)[j];
        if ((unsigned)row < N_NODES) {
            int p = atomicAdd(&g_pos[row], 1);
            g_csr_col[p] = col;
        }
    }
}

// ---------------------------------------------------------------------------
// K5: pull-gather, warp per node, 2 edges in flight per warp (R4 structure,
// self row loaded at the end to keep register pressure low -> occ ~81%).
// ---------------------------------------------------------------------------
__global__ __launch_bounds__(256) void gather_kernel(float* __restrict__ out)
{
    const int n = blockIdx.x * 8 + (threadIdx.x >> 5);
    if (n >= N_NODES) return;
    const int lane = threadIdx.x & 31;
    const int half = lane >> 4;
    const int hl   = lane & 15;

    float4 acc = make_float4(0.f, 0.f, 0.f, 0.f);

    const int start = g_off[n];
    const int end   = g_off[n + 1];

    for (int jb = start; jb < end; jb += 32) {
        const int cnt = min(32, end - jb);
        int cidx = (lane < cnt) ? g_csr_col[jb + lane] : 0;
        const int iters = (cnt + 1) >> 1;
        for (int it = 0; it < iters; it++) {
            const int tt = 2 * it + half;
            const int cc = __shfl_sync(0xffffffffu, cidx, tt & 31);
            if (tt < cnt) {
                const float4 v = __ldg((const float4*)(g_h + (size_t)cc * H) + hl);
                acc.x += v.x; acc.y += v.y; acc.z += v.z; acc.w += v.w;
            }
        }
    }

    acc.x += __shfl_down_sync(0xffffffffu, acc.x, 16);
    acc.y += __shfl_down_sync(0xffffffffu, acc.y, 16);
    acc.z += __shfl_down_sync(0xffffffffu, acc.z, 16);
    acc.w += __shfl_down_sync(0xffffffffu, acc.w, 16);

    if (lane < 16) {
        const float4 self = __ldg((const float4*)(g_h + (size_t)n * H) + hl);
        acc.x += self.x; acc.y += self.y; acc.z += self.z; acc.w += self.w;
        ((float4*)out)[(size_t)n * 16 + hl] = acc;
    }
}

// ---------------------------------------------------------------------------
// inputs: x, edge_index(int32 [2,E]), W1, b1, g1, beta1, W2, b2, g2, beta2
// Two-stream fork inside graph capture: MLP on capture stream, CSR build on s2.
// ---------------------------------------------------------------------------
extern "C" void kernel_launch(void* const* d_in, const int* in_sizes, int n_in,
                              void* d_out, int out_size)
{
    const float* x   = (const float*)d_in[0];
    const int*   ei  = (const int*)d_in[1];
    const float* W1  = (const float*)d_in[2];
    const float* b1  = (const float*)d_in[3];
    const float* g1  = (const float*)d_in[4];
    const float* be1 = (const float*)d_in[5];
    const float* W2  = (const float*)d_in[6];
    const float* b2  = (const float*)d_in[7];
    const float* g2  = (const float*)d_in[8];
    const float* be2 = (const float*)d_in[9];
    float* out = (float*)d_out;

    // one-time host-side resources (no device memory involved)
    static cudaStream_t s2 = nullptr;
    static cudaEvent_t evFork = nullptr, evJoin = nullptr;
    static void* p_deg = nullptr;
    static void* p_flag = nullptr;
    if (!s2) {
        cudaStreamCreateWithFlags(&s2, cudaStreamNonBlocking);
        cudaEventCreateWithFlags(&evFork, cudaEventDisableTiming);
        cudaEventCreateWithFlags(&evJoin, cudaEventDisableTiming);
        cudaGetSymbolAddress(&p_deg,  g_deg);
        cudaGetSymbolAddress(&p_flag, g_flag);
    }

    // fork: chain B (CSR build) on s2, independent of MLP
    cudaEventRecord(evFork, 0);
    cudaStreamWaitEvent(s2, evFork, 0);

    cudaMemsetAsync(p_deg,  0, sizeof(int) * N_NODES, s2);
    cudaMemsetAsync(p_flag, 0, sizeof(int) * NB, s2);
    hist_kernel<<<(N_EDGES / 4 + 255) / 256, 256, 0, s2>>>(ei);
    scan_kernel<<<NB, SCAN_B, 0, s2>>>();
    scatter_kernel<<<(N_EDGES / 4 + 255) / 256, 256, 0, s2>>>(ei);
    cudaEventRecord(evJoin, s2);

    // chain A (MLP) on capture stream, concurrent with chain B
    mlp_kernel<<<MLPB, 256>>>(x, W1, b1, g1, be1, W2, b2, g2, be2);

    // join, then gather (needs g_h + CSR)
    cudaStreamWaitEvent(0, evJoin, 0);
    gather_kernel<<<(N_NODES + 7) / 8, 256>>>(out);
}

// round 8
// speedup vs baseline: 1.3906x; 1.0077x over previous
#include <cuda_runtime.h>
#include <cstdint>

#define N_NODES 100000
#define N_EDGES 1250000
#define D_IN 32
#define H 64
#define SCAN_B 1024
#define NB ((N_NODES + SCAN_B - 1) / SCAN_B)   // 98
#define MLPB ((N_NODES + 31) / 32)             // 3125 blocks, 4 nodes/warp

// scratch
__device__ float g_h[(size_t)N_NODES * H];
__device__ int   g_deg[N_NODES];
__device__ int   g_off[N_NODES + 1];
__device__ int   g_pos[N_NODES];
__device__ int   g_csr_col[N_EDGES];
__device__ int   g_flag[NB];                    // decoupled-lookback: agg+1 (0 = not ready)

// ---- packed f32x2 helpers (sm_103a dual-FMA) --------------------------------
__device__ __forceinline__ unsigned long long pk2(float lo, float hi) {
    unsigned long long r;
    asm("mov.b64 %0, {%1, %2};" : "=l"(r) : "f"(lo), "f"(hi));
    return r;
}
__device__ __forceinline__ void upk2(unsigned long long v, float& lo, float& hi) {
    asm("mov.b64 {%0, %1}, %2;" : "=f"(lo), "=f"(hi) : "l"(v));
}
__device__ __forceinline__ void fma2(unsigned long long& d, unsigned long long a,
                                     unsigned long long b) {
    asm("fma.rn.f32x2 %0, %1, %2, %0;" : "+l"(d) : "l"(a), "l"(b));
}

// ---------------------------------------------------------------------------
// K1: fused node MLP (4 nodes/warp) -> g_h
// k-pair FFMA2: accumulator = (sum over even k, sum over odd k); no splat movs.
// Weights pre-paired in SMEM: sWp[kp*64 + d] = ull( W[2kp][d], W[2kp+1][d] ).
// x/h pairs come free as double2 loads from SMEM (aligned consecutive floats).
// ---------------------------------------------------------------------------
__global__ __launch_bounds__(256) void mlp_kernel(
    const float* __restrict__ x,
    const float* __restrict__ W1, const float* __restrict__ b1,
    const float* __restrict__ g1, const float* __restrict__ be1,
    const float* __restrict__ W2, const float* __restrict__ b2,
    const float* __restrict__ g2, const float* __restrict__ be2)
{
    const int tid = threadIdx.x;

    __shared__ __align__(16) unsigned long long sW1p[(D_IN / 2) * H];   // 8 KB
    __shared__ __align__(16) unsigned long long sW2p[(H / 2) * H];      // 16 KB
    __shared__ float sb1[H], sg1[H], sbe1[H];
    __shared__ float sb2[H], sg2[H], sbe2[H];
    __shared__ __align__(16) float sx[8][4][D_IN];
    __shared__ __align__(16) float sh[8][4][H];

    {
        float* w1f = (float*)sW1p;
        float* w2f = (float*)sW2p;
        for (int i = tid; i < D_IN * H; i += 256) {
            int k = i >> 6, d = i & 63;
            w1f[((k >> 1) * 64 + d) * 2 + (k & 1)] = W1[i];
        }
        for (int i = tid; i < H * H; i += 256) {
            int k = i >> 6, d = i & 63;
            w2f[((k >> 1) * 64 + d) * 2 + (k & 1)] = W2[i];
        }
    }
    if (tid < H) {
        sb1[tid] = b1[tid]; sg1[tid] = g1[tid]; sbe1[tid] = be1[tid];
        sb2[tid] = b2[tid]; sg2[tid] = g2[tid]; sbe2[tid] = be2[tid];
    }
    __syncthreads();

    const int warp = tid >> 5;
    const int lane = tid & 31;
    const int n0 = (blockIdx.x * 8 + warp) * 4;
    if (n0 >= N_NODES) return;

    #pragma unroll
    for (int j = 0; j < 4; j++)
        sx[warp][j][lane] = x[(size_t)(n0 + j) * D_IN + lane];
    __syncwarp();

    // ---- layer 1 ----  acc a0[j]: dim lane, a1[j]: dim lane+32 (k-even|k-odd halves)
    unsigned long long a0[4], a1[4];
    #pragma unroll
    for (int j = 0; j < 4; j++) {
        a0[j] = pk2(sb1[lane],      0.0f);
        a1[j] = pk2(sb1[lane + 32], 0.0f);
    }
    #pragma unroll
    for (int kp2 = 0; kp2 < D_IN / 4; kp2++) {   // 2 k-pairs (4 k) per iter
        const unsigned long long w0a = sW1p[(2 * kp2)     * 64 + lane];
        const unsigned long long w1a = sW1p[(2 * kp2)     * 64 + lane + 32];
        const unsigned long long w0b = sW1p[(2 * kp2 + 1) * 64 + lane];
        const unsigned long long w1b = sW1p[(2 * kp2 + 1) * 64 + lane + 32];
        #pragma unroll
        for (int j = 0; j < 4; j++) {
            const double2 xd = *(const double2*)&sx[warp][j][kp2 * 4];  // broadcast LDS.128
            const unsigned long long xlo = __double_as_longlong(xd.x);  // (x[4kp2],   x[4kp2+1])
            const unsigned long long xhi = __double_as_longlong(xd.y);  // (x[4kp2+2], x[4kp2+3])
            fma2(a0[j], xlo, w0a);
            fma2(a1[j], xlo, w1a);
            fma2(a0[j], xhi, w0b);
            fma2(a1[j], xhi, w1b);
        }
    }
    {
        float s[4], q[4], v0[4], v1[4];
        #pragma unroll
        for (int j = 0; j < 4; j++) {
            float l0, h0, l1, h1;
            upk2(a0[j], l0, h0); upk2(a1[j], l1, h1);
            v0[j] = l0 + h0; v1[j] = l1 + h1;
            s[j] = v0[j] + v1[j];
            q[j] = v0[j] * v0[j] + v1[j] * v1[j];
        }
        #pragma unroll
        for (int off = 16; off > 0; off >>= 1) {
            #pragma unroll
            for (int j = 0; j < 4; j++) {
                s[j] += __shfl_xor_sync(0xffffffffu, s[j], off);
                q[j] += __shfl_xor_sync(0xffffffffu, q[j], off);
            }
        }
        #pragma unroll
        for (int j = 0; j < 4; j++) {
            const float mu  = s[j] * (1.0f / H);
            const float var = q[j] * (1.0f / H) - mu * mu;
            const float inv = rsqrtf(var + 1e-5f);
            float r0 = (v0[j] - mu) * inv * sg1[lane]      + sbe1[lane];
            float r1 = (v1[j] - mu) * inv * sg1[lane + 32] + sbe1[lane + 32];
            sh[warp][j][lane]      = fmaxf(r0, 0.0f);
            sh[warp][j][lane + 32] = fmaxf(r1, 0.0f);
        }
    }
    __syncwarp();

    // ---- layer 2 ----
    unsigned long long c0[4], c1[4];
    #pragma unroll
    for (int j = 0; j < 4; j++) {
        c0[j] = pk2(sb2[lane],      0.0f);
        c1[j] = pk2(sb2[lane + 32], 0.0f);
    }
    #pragma unroll
    for (int kp2 = 0; kp2 < H / 4; kp2++) {
        const unsigned long long w0a = sW2p[(2 * kp2)     * 64 + lane];
        const unsigned long long w1a = sW2p[(2 * kp2)     * 64 + lane + 32];
        const unsigned long long w0b = sW2p[(2 * kp2 + 1) * 64 + lane];
        const unsigned long long w1b = sW2p[(2 * kp2 + 1) * 64 + lane + 32];
        #pragma unroll
        for (int j = 0; j < 4; j++) {
            const double2 hd = *(const double2*)&sh[warp][j][kp2 * 4];
            const unsigned long long hlo = __double_as_longlong(hd.x);
            const unsigned long long hhi = __double_as_longlong(hd.y);
            fma2(c0[j], hlo, w0a);
            fma2(c1[j], hlo, w1a);
            fma2(c0[j], hhi, w0b);
            fma2(c1[j], hhi, w1b);
        }
    }
    {
        float s[4], q[4], v0[4], v1[4];
        #pragma unroll
        for (int j = 0; j < 4; j++) {
            float l0, h0, l1, h1;
            upk2(c0[j], l0, h0); upk2(c1[j], l1, h1);
            v0[j] = l0 + h0; v1[j] = l1 + h1;
            s[j] = v0[j] + v1[j];
            q[j] = v0[j] * v0[j] + v1[j] * v1[j];
        }
        #pragma unroll
        for (int off = 16; off > 0; off >>= 1) {
            #pragma unroll
            for (int j = 0; j < 4; j++) {
                s[j] += __shfl_xor_sync(0xffffffffu, s[j], off);
                q[j] += __shfl_xor_sync(0xffffffffu, q[j], off);
            }
        }
        #pragma unroll
        for (int j = 0; j < 4; j++) {
            const float mu  = s[j] * (1.0f / H);
            const float var = q[j] * (1.0f / H) - mu * mu;
            const float inv = rsqrtf(var + 1e-5f);
            float r0 = (v0[j] - mu) * inv * sg2[lane]      + sbe2[lane];
            float r1 = (v1[j] - mu) * inv * sg2[lane + 32] + sbe2[lane + 32];
            const size_t base = (size_t)(n0 + j) * H;
            g_h[base + lane]      = fmaxf(r0, 0.0f);
            g_h[base + lane + 32] = fmaxf(r1, 0.0f);
        }
    }
}

// ---------------------------------------------------------------------------
// K2b: degree histogram (4 edges/thread, int4 loads, fire-and-forget atomics)
// ---------------------------------------------------------------------------
__global__ __launch_bounds__(256) void hist_kernel(const int* __restrict__ ei)
{
    const int e4 = (blockIdx.x * 256 + threadIdx.x) * 4;
    if (e4 >= N_EDGES) return;
    const int4 rows = *(const int4*)&ei[e4];
    #pragma unroll
    for (int j = 0; j < 4; j++) {
        const int row = (&rows.x)[j];
        if ((unsigned)row < N_NODES) atomicAdd(&g_deg[row], 1);
    }
}

// ---------------------------------------------------------------------------
// K3b: single-kernel exclusive scan (decoupled lookback; 98 blocks all wave-1)
// ---------------------------------------------------------------------------
__global__ __launch_bounds__(SCAN_B) void scan_kernel()
{
    __shared__ int wsum[32];
    __shared__ int sprefix;
    const int t   = threadIdx.x;
    const int bid = blockIdx.x;
    const int i   = bid * SCAN_B + t;

    int v = (i < N_NODES) ? g_deg[i] : 0;
    const int orig = v;
    #pragma unroll
    for (int o = 1; o < 32; o <<= 1) {
        int n = __shfl_up_sync(0xffffffffu, v, o);
        if ((t & 31) >= o) v += n;
    }
    if ((t & 31) == 31) wsum[t >> 5] = v;
    __syncthreads();
    if (t < 32) {
        int w = wsum[t];
        #pragma unroll
        for (int o = 1; o < 32; o <<= 1) {
            int n = __shfl_up_sync(0xffffffffu, w, o);
            if (t >= o) w += n;
        }
        wsum[t] = w;
    }
    __syncthreads();
    const int base = (t >= 32) ? wsum[(t >> 5) - 1] : 0;
    const int incl = v + base;

    if (t == SCAN_B - 1) ((volatile int*)g_flag)[bid] = incl + 1;

    if (t < 32) {
        int sum = 0;
        for (int j0 = bid - 1; j0 >= 0; j0 -= 32) {
            const int j = j0 - t;
            int av = 0;
            if (j >= 0) {
                while ((av = ((volatile int*)g_flag)[j]) == 0) {}
                av -= 1;
            }
            #pragma unroll
            for (int o = 16; o > 0; o >>= 1)
                av += __shfl_xor_sync(0xffffffffu, av, o);
            sum += av;
        }
        if (t == 0) sprefix = sum;
    }
    __syncthreads();

    if (i < N_NODES) {
        const int o = sprefix + incl - orig;
        g_off[i] = o;
        g_pos[i] = o;
    }
    if (i == 0) g_off[N_NODES] = N_EDGES;
}

// ---------------------------------------------------------------------------
// K4b: scatter column ids into CSR slots (4 edges/thread, int4 index loads)
// ---------------------------------------------------------------------------
__global__ __launch_bounds__(256) void scatter_kernel(const int* __restrict__ ei)
{
    const int e4 = (blockIdx.x * 256 + threadIdx.x) * 4;
    if (e4 >= N_EDGES) return;
    const int4 rows = *(const int4*)&ei[e4];
    const int4 cols = *(const int4*)&ei[N_EDGES + e4];
    #pragma unroll
    for (int j = 0; j < 4; j++) {
        const int row = (&rows.x)[j];
        const int col = (&cols.x)[j];
        if ((unsigned)row < N_NODES) {
            int p = atomicAdd(&g_pos[row], 1);
            g_csr_col[p] = col;
        }
    }
}

// ---------------------------------------------------------------------------
// K5: pull-gather, warp per node, 2 edges in flight per warp (R4 structure).
// ---------------------------------------------------------------------------
__global__ __launch_bounds__(256) void gather_kernel(float* __restrict__ out)
{
    const int n = blockIdx.x * 8 + (threadIdx.x >> 5);
    if (n >= N_NODES) return;
    const int lane = threadIdx.x & 31;
    const int half = lane >> 4;
    const int hl   = lane & 15;

    float4 acc = make_float4(0.f, 0.f, 0.f, 0.f);

    const int start = g_off[n];
    const int end   = g_off[n + 1];

    for (int jb = start; jb < end; jb += 32) {
        const int cnt = min(32, end - jb);
        int cidx = (lane < cnt) ? g_csr_col[jb + lane] : 0;
        const int iters = (cnt + 1) >> 1;
        for (int it = 0; it < iters; it++) {
            const int tt = 2 * it + half;
            const int cc = __shfl_sync(0xffffffffu, cidx, tt & 31);
            if (tt < cnt) {
                const float4 v = __ldg((const float4*)(g_h + (size_t)cc * H) + hl);
                acc.x += v.x; acc.y += v.y; acc.z += v.z; acc.w += v.w;
            }
        }
    }

    acc.x += __shfl_down_sync(0xffffffffu, acc.x, 16);
    acc.y += __shfl_down_sync(0xffffffffu, acc.y, 16);
    acc.z += __shfl_down_sync(0xffffffffu, acc.z, 16);
    acc.w += __shfl_down_sync(0xffffffffu, acc.w, 16);

    if (lane < 16) {
        const float4 self = __ldg((const float4*)(g_h + (size_t)n * H) + hl);
        acc.x += self.x; acc.y += self.y; acc.z += self.z; acc.w += self.w;
        ((float4*)out)[(size_t)n * 16 + hl] = acc;
    }
}

// ---------------------------------------------------------------------------
// inputs: x, edge_index(int32 [2,E]), W1, b1, g1, beta1, W2, b2, g2, beta2
// Two-stream fork inside graph capture: MLP on capture stream, CSR build on s2.
// ---------------------------------------------------------------------------
extern "C" void kernel_launch(void* const* d_in, const int* in_sizes, int n_in,
                              void* d_out, int out_size)
{
    const float* x   = (const float*)d_in[0];
    const int*   ei  = (const int*)d_in[1];
    const float* W1  = (const float*)d_in[2];
    const float* b1  = (const float*)d_in[3];
    const float* g1  = (const float*)d_in[4];
    const float* be1 = (const float*)d_in[5];
    const float* W2  = (const float*)d_in[6];
    const float* b2  = (const float*)d_in[7];
    const float* g2  = (const float*)d_in[8];
    const float* be2 = (const float*)d_in[9];
    float* out = (float*)d_out;

    static cudaStream_t s2 = nullptr;
    static cudaEvent_t evFork = nullptr, evJoin = nullptr;
    static void* p_deg = nullptr;
    static void* p_flag = nullptr;
    if (!s2) {
        cudaStreamCreateWithFlags(&s2, cudaStreamNonBlocking);
        cudaEventCreateWithFlags(&evFork, cudaEventDisableTiming);
        cudaEventCreateWithFlags(&evJoin, cudaEventDisableTiming);
        cudaGetSymbolAddress(&p_deg,  g_deg);
        cudaGetSymbolAddress(&p_flag, g_flag);
    }

    cudaEventRecord(evFork, 0);
    cudaStreamWaitEvent(s2, evFork, 0);

    cudaMemsetAsync(p_deg,  0, sizeof(int) * N_NODES, s2);
    cudaMemsetAsync(p_flag, 0, sizeof(int) * NB, s2);
    hist_kernel<<<(N_EDGES / 4 + 255) / 256, 256, 0, s2>>>(ei);
    scan_kernel<<<NB, SCAN_B, 0, s2>>>();
    scatter_kernel<<<(N_EDGES / 4 + 255) / 256, 256, 0, s2>>>(ei);
    cudaEventRecord(evJoin, s2);

    mlp_kernel<<<MLPB, 256>>>(x, W1, b1, g1, be1, W2, b2, g2, be2);

    cudaStreamWaitEvent(0, evJoin, 0);
    gather_kernel<<<(N_NODES + 7) / 8, 256>>>(out);
}

// round 9
// speedup vs baseline: 1.5256x; 1.0971x over previous
#include <cuda_runtime.h>
#include <cstdint>

#define N_NODES 100000
#define N_EDGES 1250000
#define D_IN 32
#define H 64
#define SCAN_B 1024
#define NB ((N_NODES + SCAN_B - 1) / SCAN_B)   // 98
#define NPW 8                                   // nodes per warp
#define MLPB ((N_NODES + 8 * NPW - 1) / (8 * NPW))   // 1563 blocks

// scratch
__device__ float g_h[(size_t)N_NODES * H];
__device__ int   g_deg[N_NODES];
__device__ int   g_off[N_NODES + 1];
__device__ int   g_pos[N_NODES];
__device__ int   g_csr_col[N_EDGES];
__device__ int   g_flag[NB];                    // decoupled-lookback: agg+1 (0 = not ready)

// ---- packed f32x2 helpers (sm_103a dual-FMA) --------------------------------
__device__ __forceinline__ unsigned long long pk2(float lo, float hi) {
    unsigned long long r;
    asm("mov.b64 %0, {%1, %2};" : "=l"(r) : "f"(lo), "f"(hi));
    return r;
}
__device__ __forceinline__ void upk2(unsigned long long v, float& lo, float& hi) {
    asm("mov.b64 {%0, %1}, %2;" : "=f"(lo), "=f"(hi) : "l"(v));
}
__device__ __forceinline__ void fma2(unsigned long long& d, unsigned long long a,
                                     unsigned long long b) {
    asm("fma.rn.f32x2 %0, %1, %2, %0;" : "+l"(d) : "l"(a), "l"(b));
}

// ---------------------------------------------------------------------------
// K1: fused node MLP, 8 nodes per warp (halves weight-LDS per node vs 4/warp).
// k-pair FFMA2: accumulator = (sum over even k, sum over odd k).
// Weights pre-paired in SMEM: sWp[kp*64 + d] = ull( W[2kp][d], W[2kp+1][d] ).
// ---------------------------------------------------------------------------
__global__ __launch_bounds__(256) void mlp_kernel(
    const float* __restrict__ x,
    const float* __restrict__ W1, const float* __restrict__ b1,
    const float* __restrict__ g1, const float* __restrict__ be1,
    const float* __restrict__ W2, const float* __restrict__ b2,
    const float* __restrict__ g2, const float* __restrict__ be2)
{
    const int tid = threadIdx.x;

    __shared__ __align__(16) unsigned long long sW1p[(D_IN / 2) * H];   // 8 KB
    __shared__ __align__(16) unsigned long long sW2p[(H / 2) * H];      // 16 KB
    __shared__ float sb1[H], sg1[H], sbe1[H];
    __shared__ float sb2[H], sg2[H], sbe2[H];
    __shared__ __align__(16) float sx[8][NPW][D_IN];   // 8 KB
    __shared__ __align__(16) float sh[8][NPW][H];      // 16 KB

    {
        float* w1f = (float*)sW1p;
        float* w2f = (float*)sW2p;
        for (int i = tid; i < D_IN * H; i += 256) {
            int k = i >> 6, d = i & 63;
            w1f[((k >> 1) * 64 + d) * 2 + (k & 1)] = W1[i];
        }
        for (int i = tid; i < H * H; i += 256) {
            int k = i >> 6, d = i & 63;
            w2f[((k >> 1) * 64 + d) * 2 + (k & 1)] = W2[i];
        }
    }
    if (tid < H) {
        sb1[tid] = b1[tid]; sg1[tid] = g1[tid]; sbe1[tid] = be1[tid];
        sb2[tid] = b2[tid]; sg2[tid] = g2[tid]; sbe2[tid] = be2[tid];
    }
    __syncthreads();

    const int warp = tid >> 5;
    const int lane = tid & 31;
    const int n0 = (blockIdx.x * 8 + warp) * NPW;
    if (n0 >= N_NODES) return;

    #pragma unroll
    for (int j = 0; j < NPW; j++) {
        const int nj = min(n0 + j, N_NODES - 1);      // clamp (tail-safe)
        sx[warp][j][lane] = x[(size_t)nj * D_IN + lane];
    }
    __syncwarp();

    // ---- layer 1 ----
    unsigned long long a0[NPW], a1[NPW];
    #pragma unroll
    for (int j = 0; j < NPW; j++) {
        a0[j] = pk2(sb1[lane],      0.0f);
        a1[j] = pk2(sb1[lane + 32], 0.0f);
    }
    #pragma unroll
    for (int kp2 = 0; kp2 < D_IN / 4; kp2++) {        // 2 k-pairs (4 k) per iter
        const unsigned long long w0a = sW1p[(2 * kp2)     * 64 + lane];
        const unsigned long long w1a = sW1p[(2 * kp2)     * 64 + lane + 32];
        const unsigned long long w0b = sW1p[(2 * kp2 + 1) * 64 + lane];
        const unsigned long long w1b = sW1p[(2 * kp2 + 1) * 64 + lane + 32];
        #pragma unroll
        for (int j = 0; j < NPW; j++) {
            const double2 xd = *(const double2*)&sx[warp][j][kp2 * 4];  // broadcast LDS.128
            const unsigned long long xlo = __double_as_longlong(xd.x);
            const unsigned long long xhi = __double_as_longlong(xd.y);
            fma2(a0[j], xlo, w0a);
            fma2(a1[j], xlo, w1a);
            fma2(a0[j], xhi, w0b);
            fma2(a1[j], xhi, w1b);
        }
    }
    // LN + ReLU, batched in groups of 4 to pipeline shfl latency
    #pragma unroll
    for (int g = 0; g < NPW; g += 4) {
        float s[4], q[4], v0[4], v1[4];
        #pragma unroll
        for (int u = 0; u < 4; u++) {
            float l0, h0, l1, h1;
            upk2(a0[g + u], l0, h0); upk2(a1[g + u], l1, h1);
            v0[u] = l0 + h0; v1[u] = l1 + h1;
            s[u] = v0[u] + v1[u];
            q[u] = v0[u] * v0[u] + v1[u] * v1[u];
        }
        #pragma unroll
        for (int off = 16; off > 0; off >>= 1) {
            #pragma unroll
            for (int u = 0; u < 4; u++) {
                s[u] += __shfl_xor_sync(0xffffffffu, s[u], off);
                q[u] += __shfl_xor_sync(0xffffffffu, q[u], off);
            }
        }
        #pragma unroll
        for (int u = 0; u < 4; u++) {
            const float mu  = s[u] * (1.0f / H);
            const float var = q[u] * (1.0f / H) - mu * mu;
            const float inv = rsqrtf(var + 1e-5f);
            float r0 = (v0[u] - mu) * inv * sg1[lane]      + sbe1[lane];
            float r1 = (v1[u] - mu) * inv * sg1[lane + 32] + sbe1[lane + 32];
            sh[warp][g + u][lane]      = fmaxf(r0, 0.0f);
            sh[warp][g + u][lane + 32] = fmaxf(r1, 0.0f);
        }
    }
    __syncwarp();

    // ---- layer 2 ----
    unsigned long long c0[NPW], c1[NPW];
    #pragma unroll
    for (int j = 0; j < NPW; j++) {
        c0[j] = pk2(sb2[lane],      0.0f);
        c1[j] = pk2(sb2[lane + 32], 0.0f);
    }
    #pragma unroll
    for (int kp2 = 0; kp2 < H / 4; kp2++) {
        const unsigned long long w0a = sW2p[(2 * kp2)     * 64 + lane];
        const unsigned long long w1a = sW2p[(2 * kp2)     * 64 + lane + 32];
        const unsigned long long w0b = sW2p[(2 * kp2 + 1) * 64 + lane];
        const unsigned long long w1b = sW2p[(2 * kp2 + 1) * 64 + lane + 32];
        #pragma unroll
        for (int j = 0; j < NPW; j++) {
            const double2 hd = *(const double2*)&sh[warp][j][kp2 * 4];
            const unsigned long long hlo = __double_as_longlong(hd.x);
            const unsigned long long hhi = __double_as_longlong(hd.y);
            fma2(c0[j], hlo, w0a);
            fma2(c1[j], hlo, w1a);
            fma2(c0[j], hhi, w0b);
            fma2(c1[j], hhi, w1b);
        }
    }
    #pragma unroll
    for (int g = 0; g < NPW; g += 4) {
        float s[4], q[4], v0[4], v1[4];
        #pragma unroll
        for (int u = 0; u < 4; u++) {
            float l0, h0, l1, h1;
            upk2(c0[g + u], l0, h0); upk2(c1[g + u], l1, h1);
            v0[u] = l0 + h0; v1[u] = l1 + h1;
            s[u] = v0[u] + v1[u];
            q[u] = v0[u] * v0[u] + v1[u] * v1[u];
        }
        #pragma unroll
        for (int off = 16; off > 0; off >>= 1) {
            #pragma unroll
            for (int u = 0; u < 4; u++) {
                s[u] += __shfl_xor_sync(0xffffffffu, s[u], off);
                q[u] += __shfl_xor_sync(0xffffffffu, q[u], off);
            }
        }
        #pragma unroll
        for (int u = 0; u < 4; u++) {
            const int nj = n0 + g + u;
            if (nj < N_NODES) {
                const float mu  = s[u] * (1.0f / H);
                const float var = q[u] * (1.0f / H) - mu * mu;
                const float inv = rsqrtf(var + 1e-5f);
                float r0 = (v0[u] - mu) * inv * sg2[lane]      + sbe2[lane];
                float r1 = (v1[u] - mu) * inv * sg2[lane + 32] + sbe2[lane + 32];
                const size_t base = (size_t)nj * H;
                g_h[base + lane]      = fmaxf(r0, 0.0f);
                g_h[base + lane + 32] = fmaxf(r1, 0.0f);
            }
        }
    }
}

// ---------------------------------------------------------------------------
// K2b: degree histogram (4 edges/thread, int4 loads, fire-and-forget atomics)
// ---------------------------------------------------------------------------
__global__ __launch_bounds__(256) void hist_kernel(const int* __restrict__ ei)
{
    const int e4 = (blockIdx.x * 256 + threadIdx.x) * 4;
    if (e4 >= N_EDGES) return;
    const int4 rows = *(const int4*)&ei[e4];
    #pragma unroll
    for (int j = 0; j < 4; j++) {
        const int row = (&rows.x)[j];
        if ((unsigned)row < N_NODES) atomicAdd(&g_deg[row], 1);
    }
}

// ---------------------------------------------------------------------------
// K3b: single-kernel exclusive scan (decoupled lookback; 98 blocks all wave-1)
// ---------------------------------------------------------------------------
__global__ __launch_bounds__(SCAN_B) void scan_kernel()
{
    __shared__ int wsum[32];
    __shared__ int sprefix;
    const int t   = threadIdx.x;
    const int bid = blockIdx.x;
    const int i   = bid * SCAN_B + t;

    int v = (i < N_NODES) ? g_deg[i] : 0;
    const int orig = v;
    #pragma unroll
    for (int o = 1; o < 32; o <<= 1) {
        int n = __shfl_up_sync(0xffffffffu, v, o);
        if ((t & 31) >= o) v += n;
    }
    if ((t & 31) == 31) wsum[t >> 5] = v;
    __syncthreads();
    if (t < 32) {
        int w = wsum[t];
        #pragma unroll
        for (int o = 1; o < 32; o <<= 1) {
            int n = __shfl_up_sync(0xffffffffu, w, o);
            if (t >= o) w += n;
        }
        wsum[t] = w;
    }
    __syncthreads();
    const int base = (t >= 32) ? wsum[(t >> 5) - 1] : 0;
    const int incl = v + base;

    if (t == SCAN_B - 1) ((volatile int*)g_flag)[bid] = incl + 1;

    if (t < 32) {
        int sum = 0;
        for (int j0 = bid - 1; j0 >= 0; j0 -= 32) {
            const int j = j0 - t;
            int av = 0;
            if (j >= 0) {
                while ((av = ((volatile int*)g_flag)[j]) == 0) {}
                av -= 1;
            }
            #pragma unroll
            for (int o = 16; o > 0; o >>= 1)
                av += __shfl_xor_sync(0xffffffffu, av, o);
            sum += av;
        }
        if (t == 0) sprefix = sum;
    }
    __syncthreads();

    if (i < N_NODES) {
        const int o = sprefix + incl - orig;
        g_off[i] = o;
        g_pos[i] = o;
    }
    if (i == 0) g_off[N_NODES] = N_EDGES;
}

// ---------------------------------------------------------------------------
// K4b: scatter column ids into CSR slots (4 edges/thread, int4 index loads)
// ---------------------------------------------------------------------------
__global__ __launch_bounds__(256) void scatter_kernel(const int* __restrict__ ei)
{
    const int e4 = (blockIdx.x * 256 + threadIdx.x) * 4;
    if (e4 >= N_EDGES) return;
    const int4 rows = *(const int4*)&ei[e4];
    const int4 cols = *(const int4*)&ei[N_EDGES + e4];
    #pragma unroll
    for (int j = 0; j < 4; j++) {
        const int row = (&rows.x)[j];
        const int col = (&cols.x)[j];
        if ((unsigned)row < N_NODES) {
            int p = atomicAdd(&g_pos[row], 1);
            g_csr_col[p] = col;
        }
    }
}

// ---------------------------------------------------------------------------
// K5: pull-gather, warp per node, 2 edges in flight per warp (R4 structure).
// ---------------------------------------------------------------------------
__global__ __launch_bounds__(256) void gather_kernel(float* __restrict__ out)
{
    const int n = blockIdx.x * 8 + (threadIdx.x >> 5);
    if (n >= N_NODES) return;
    const int lane = threadIdx.x & 31;
    const int half = lane >> 4;
    const int hl   = lane & 15;

    float4 acc = make_float4(0.f, 0.f, 0.f, 0.f);

    const int start = g_off[n];
    const int end   = g_off[n + 1];

    for (int jb = start; jb < end; jb += 32) {
        const int cnt = min(32, end - jb);
        int cidx = (lane < cnt) ? g_csr_col[jb + lane] : 0;
        const int iters = (cnt + 1) >> 1;
        for (int it = 0; it < iters; it++) {
            const int tt = 2 * it + half;
            const int cc = __shfl_sync(0xffffffffu, cidx, tt & 31);
            if (tt < cnt) {
                const float4 v = __ldg((const float4*)(g_h + (size_t)cc * H) + hl);
                acc.x += v.x; acc.y += v.y; acc.z += v.z; acc.w += v.w;
            }
        }
    }

    acc.x += __shfl_down_sync(0xffffffffu, acc.x, 16);
    acc.y += __shfl_down_sync(0xffffffffu, acc.y, 16);
    acc.z += __shfl_down_sync(0xffffffffu, acc.z, 16);
    acc.w += __shfl_down_sync(0xffffffffu, acc.w, 16);

    if (lane < 16) {
        const float4 self = __ldg((const float4*)(g_h + (size_t)n * H) + hl);
        acc.x += self.x; acc.y += self.y; acc.z += self.z; acc.w += self.w;
        ((float4*)out)[(size_t)n * 16 + hl] = acc;
    }
}

// ---------------------------------------------------------------------------
// inputs: x, edge_index(int32 [2,E]), W1, b1, g1, beta1, W2, b2, g2, beta2
// Two-stream fork inside graph capture: MLP on capture stream, CSR build on s2.
// ---------------------------------------------------------------------------
extern "C" void kernel_launch(void* const* d_in, const int* in_sizes, int n_in,
                              void* d_out, int out_size)
{
    const float* x   = (const float*)d_in[0];
    const int*   ei  = (const int*)d_in[1];
    const float* W1  = (const float*)d_in[2];
    const float* b1  = (const float*)d_in[3];
    const float* g1  = (const float*)d_in[4];
    const float* be1 = (const float*)d_in[5];
    const float* W2  = (const float*)d_in[6];
    const float* b2  = (const float*)d_in[7];
    const float* g2  = (const float*)d_in[8];
    const float* be2 = (const float*)d_in[9];
    float* out = (float*)d_out;

    static cudaStream_t s2 = nullptr;
    static cudaEvent_t evFork = nullptr, evJoin = nullptr;
    static void* p_deg = nullptr;
    static void* p_flag = nullptr;
    if (!s2) {
        cudaStreamCreateWithFlags(&s2, cudaStreamNonBlocking);
        cudaEventCreateWithFlags(&evFork, cudaEventDisableTiming);
        cudaEventCreateWithFlags(&evJoin, cudaEventDisableTiming);
        cudaGetSymbolAddress(&p_deg,  g_deg);
        cudaGetSymbolAddress(&p_flag, g_flag);
    }

    cudaEventRecord(evFork, 0);
    cudaStreamWaitEvent(s2, evFork, 0);

    cudaMemsetAsync(p_deg,  0, sizeof(int) * N_NODES, s2);
    cudaMemsetAsync(p_flag, 0, sizeof(int) * NB, s2);
    hist_kernel<<<(N_EDGES / 4 + 255) / 256, 256, 0, s2>>>(ei);
    scan_kernel<<<NB, SCAN_B, 0, s2>>>();
    scatter_kernel<<<(N_EDGES / 4 + 255) / 256, 256, 0, s2>>>(ei);
    cudaEventRecord(evJoin, s2);

    mlp_kernel<<<MLPB, 256>>>(x, W1, b1, g1, be1, W2, b2, g2, be2);

    cudaStreamWaitEvent(0, evJoin, 0);
    gather_kernel<<<(N_NODES + 7) / 8, 256>>>(out);
}